// round 4
// baseline (speedup 1.0000x reference)
#include <cuda_runtime.h>
#include <cstdint>

// Problem constants
constexpr int HID   = 1024;
constexpr int INTER = 4096;
constexpr int NE    = 8;
constexpr int NT    = 8192;

// Tiling
constexpr int BM = 128;
constexpr int BN = 128;
constexpr int BK = 16;
// Total routed pairs = TOP_K * NT = 16384 -> sum_e ceil(cnt_e/BM) <= 16384/128 + 8 = 136
constexpr int MAX_TILES = (2 * NT) / BM + NE;   // 136

// ---------------- device scratch (no allocations allowed) ----------------
__device__ int   g_tok[NE][NT];
__device__ float g_wt [NE][NT];
__device__ int   g_cnt[NE];
__device__ int   g_top1[NE];
__device__ float g_psum[NE];
__device__ int   g_tile_e[MAX_TILES];
__device__ int   g_tile_base[MAX_TILES];
__device__ float g_h[(long long)MAX_TILES * BM * INTER];   // ~285 MB fp32 scratch

// ---------------- helpers ----------------
__device__ __forceinline__ void cp_async16(void* smem_dst, const void* gmem_src){
    uint32_t d = (uint32_t)__cvta_generic_to_shared(smem_dst);
    asm volatile("cp.async.cg.shared.global [%0], [%1], 16;\n" :: "r"(d), "l"(gmem_src));
}
__device__ __forceinline__ void cp_commit(){ asm volatile("cp.async.commit_group;\n" ::: "memory"); }
__device__ __forceinline__ void cp_wait1(){ asm volatile("cp.async.wait_group 1;\n" ::: "memory"); }

// Proper f32 -> tf32 conversion (round-to-nearest).
__device__ __forceinline__ uint32_t to_tf32(float f){
    uint32_t r;
    asm volatile("cvt.rna.tf32.f32 %0, %1;\n" : "=r"(r) : "f"(f));
    return r;
}

__device__ __forceinline__ void mma8(float4& d,
                                     uint32_t a0, uint32_t a1, uint32_t a2, uint32_t a3,
                                     uint32_t b0, uint32_t b1){
    asm volatile("mma.sync.aligned.m16n8k8.row.col.f32.tf32.tf32.f32 "
                 "{%0,%1,%2,%3}, {%4,%5,%6,%7}, {%8,%9}, {%0,%1,%2,%3};\n"
                 : "+f"(d.x), "+f"(d.y), "+f"(d.z), "+f"(d.w)
                 : "r"(a0), "r"(a1), "r"(a2), "r"(a3), "r"(b0), "r"(b1));
}

// ---------------- kernel 0: zero output + counters ----------------
__global__ void k_init(float* out, int n){
    int stride = gridDim.x * blockDim.x;
    for (int i = blockIdx.x * blockDim.x + threadIdx.x; i < n; i += stride) out[i] = 0.f;
    if (blockIdx.x == 0 && threadIdx.x < NE){
        g_cnt[threadIdx.x]  = 0;
        g_top1[threadIdx.x] = 0;
        g_psum[threadIdx.x] = 0.f;
    }
}

// ---------------- kernel 1: router (1 warp per token) ----------------
__global__ void k_router(const float* __restrict__ x, const float* __restrict__ rw){
    int t = blockIdx.x * (blockDim.x >> 5) + (threadIdx.x >> 5);
    int lane = threadIdx.x & 31;
    if (t >= NT) return;
    const float4* xr = reinterpret_cast<const float4*>(x + (size_t)t * HID);
    float acc[NE];
#pragma unroll
    for (int e = 0; e < NE; e++) acc[e] = 0.f;
#pragma unroll
    for (int j = 0; j < 8; j++){
        float4 xv = xr[lane + 32 * j];
#pragma unroll
        for (int e = 0; e < NE; e++){
            float4 wv = reinterpret_cast<const float4*>(rw + e * HID)[lane + 32 * j];
            acc[e] += xv.x * wv.x + xv.y * wv.y + xv.z * wv.z + xv.w * wv.w;
        }
    }
#pragma unroll
    for (int o = 16; o > 0; o >>= 1)
#pragma unroll
        for (int e = 0; e < NE; e++)
            acc[e] += __shfl_xor_sync(0xffffffffu, acc[e], o);

    if (lane == 0){
        float m = acc[0];
#pragma unroll
        for (int e = 1; e < NE; e++) m = fmaxf(m, acc[e]);
        float p[NE]; float s = 0.f;
#pragma unroll
        for (int e = 0; e < NE; e++){ p[e] = expf(acc[e] - m); s += p[e]; }
        float inv = 1.f / s;
#pragma unroll
        for (int e = 0; e < NE; e++) p[e] *= inv;
        // top-2 (ties -> lower index, matching jax top_k)
        int i1 = 0;
#pragma unroll
        for (int e = 1; e < NE; e++) if (p[e] > p[i1]) i1 = e;
        int i2 = (i1 == 0) ? 1 : 0;
#pragma unroll
        for (int e = 0; e < NE; e++) if (e != i1 && p[e] > p[i2]) i2 = e;
        float w1 = p[i1], w2 = p[i2];
        float rs = 1.f / (w1 + w2);
        w1 *= rs; w2 *= rs;
        int pos1 = atomicAdd(&g_cnt[i1], 1);
        g_tok[i1][pos1] = t; g_wt[i1][pos1] = w1;
        int pos2 = atomicAdd(&g_cnt[i2], 1);
        g_tok[i2][pos2] = t; g_wt[i2][pos2] = w2;
        atomicAdd(&g_top1[i1], 1);
#pragma unroll
        for (int e = 0; e < NE; e++) atomicAdd(&g_psum[e], p[e]);
    }
}

// ---------------- kernel 2: tile map + aux loss ----------------
__global__ void k_setup(float* out, int out_size){
    if (threadIdx.x != 0 || blockIdx.x != 0) return;
    int nt = 0;
    for (int e = 0; e < NE; e++){
        int c = g_cnt[e];
        for (int b = 0; b < c; b += BM){
            g_tile_e[nt] = e; g_tile_base[nt] = b; nt++;
        }
    }
    for (; nt < MAX_TILES; nt++) g_tile_e[nt] = -1;

    float aux = 0.f;
    for (int e = 0; e < NE; e++)
        aux += ((float)g_top1[e] / (float)NT) * (g_psum[e] / (float)NT);
    aux *= (float)NE;
    if (out_size > NT * HID) out[NT * HID] = aux;
}

// ---------------- kernel 3: grouped GEMM1 (gather x @ W1, SiLU) ----------------
__global__ void __launch_bounds__(256, 2) k_gemm1(const float* __restrict__ x,
                                                  const float* __restrict__ w1){
    int e = g_tile_e[blockIdx.y];
    if (e < 0) return;
    int base = g_tile_base[blockIdx.y];
    int cnt  = g_cnt[e];
    int n0   = blockIdx.x * BN;

    __shared__ __align__(16) float As[2][BM][BK + 4];  // pitch 20 -> conflict-free A frags
    __shared__ __align__(16) float Bs[2][BK][BN + 8];  // pitch 136 -> conflict-free B frags
    __shared__ int   s_tok[BM];

    int tid = threadIdx.x;
    if (tid < BM){
        int idx = base + tid;
        if (idx >= cnt) idx = cnt - 1;      // clamp pad rows (weight 0 later)
        s_tok[tid] = g_tok[e][idx];
    }
    __syncthreads();

    const float* wp = w1 + (size_t)e * HID * INTER;

    int arow = tid >> 2;                    // 0..63
    int af4  = (tid & 3) * 4;
    int brow = tid >> 5;                    // 0..7
    int bf4  = (tid & 31) * 4;

    const float* asrc0 = x + (size_t)s_tok[arow]      * HID + af4;
    const float* asrc1 = x + (size_t)s_tok[arow + 64] * HID + af4;

    float4 c[2][8];
#pragma unroll
    for (int mi = 0; mi < 2; mi++)
#pragma unroll
        for (int ni = 0; ni < 8; ni++) c[mi][ni] = make_float4(0.f, 0.f, 0.f, 0.f);

    int w    = tid >> 5;
    int lane = tid & 31;
    int wrow = (w & 3) * 32;
    int wcol = (w >> 2) * 64;
    int g    = lane >> 2;
    int q    = lane & 3;

    auto load_tile = [&](int buf, int k0){
        cp_async16(&As[buf][arow     ][af4], asrc0 + k0);
        cp_async16(&As[buf][arow + 64][af4], asrc1 + k0);
        cp_async16(&Bs[buf][brow     ][bf4], wp + (size_t)(k0 + brow    ) * INTER + n0 + bf4);
        cp_async16(&Bs[buf][brow + 8 ][bf4], wp + (size_t)(k0 + brow + 8) * INTER + n0 + bf4);
    };

    load_tile(0, 0);
    cp_commit();

    const int KT = HID / BK;   // 64
    for (int it = 0; it < KT; it++){
        int cur = it & 1;
        if (it + 1 < KT) load_tile(cur ^ 1, (it + 1) * BK);
        cp_commit();
        cp_wait1();
        __syncthreads();
#pragma unroll
        for (int kk = 0; kk < 2; kk++){
            int ko = kk * 8;
            uint32_t a[2][4];
#pragma unroll
            for (int mi = 0; mi < 2; mi++){
                int rb = wrow + mi * 16;
                a[mi][0] = to_tf32(As[cur][rb + g    ][ko + q    ]);
                a[mi][1] = to_tf32(As[cur][rb + g + 8][ko + q    ]);
                a[mi][2] = to_tf32(As[cur][rb + g    ][ko + q + 4]);
                a[mi][3] = to_tf32(As[cur][rb + g + 8][ko + q + 4]);
            }
#pragma unroll
            for (int ni = 0; ni < 8; ni++){
                int col = wcol + ni * 8 + g;
                uint32_t b0 = to_tf32(Bs[cur][ko + q    ][col]);
                uint32_t b1 = to_tf32(Bs[cur][ko + q + 4][col]);
#pragma unroll
                for (int mi = 0; mi < 2; mi++)
                    mma8(c[mi][ni], a[mi][0], a[mi][1], a[mi][2], a[mi][3], b0, b1);
            }
        }
        __syncthreads();
    }

    // epilogue: SiLU, store to h scratch (pad rows written but weight==0 later)
    long long hbase = (long long)blockIdx.y * BM;
#pragma unroll
    for (int mi = 0; mi < 2; mi++){
        int r0 = wrow + mi * 16 + g;
#pragma unroll
        for (int ni = 0; ni < 8; ni++){
            int col = n0 + wcol + ni * 8 + q * 2;
            float4 v = c[mi][ni];
            float2 u0, u1;
            u0.x = v.x / (1.f + __expf(-v.x));
            u0.y = v.y / (1.f + __expf(-v.y));
            u1.x = v.z / (1.f + __expf(-v.z));
            u1.y = v.w / (1.f + __expf(-v.w));
            *reinterpret_cast<float2*>(&g_h[(hbase + r0    ) * INTER + col]) = u0;
            *reinterpret_cast<float2*>(&g_h[(hbase + r0 + 8) * INTER + col]) = u1;
        }
    }
}

// ---------------- kernel 4: grouped GEMM2 (h @ W2, weighted scatter) ----------------
__global__ void __launch_bounds__(256, 2) k_gemm2(const float* __restrict__ w2,
                                                  float* __restrict__ out){
    int e = g_tile_e[blockIdx.y];
    if (e < 0) return;
    int base = g_tile_base[blockIdx.y];
    int cnt  = g_cnt[e];
    int n0   = blockIdx.x * BN;

    __shared__ __align__(16) float As[2][BM][BK + 4];
    __shared__ __align__(16) float Bs[2][BK][BN + 8];
    __shared__ int   s_tok[BM];
    __shared__ float s_w[BM];

    int tid = threadIdx.x;
    if (tid < BM){
        int idx = base + tid;
        bool valid = idx < cnt;
        int ci = valid ? idx : (cnt - 1);
        s_tok[tid] = g_tok[e][ci];
        s_w[tid]   = valid ? g_wt[e][idx] : 0.f;
    }

    const float* wp = w2 + (size_t)e * INTER * HID;

    int arow = tid >> 2;
    int af4  = (tid & 3) * 4;
    int brow = tid >> 5;
    int bf4  = (tid & 31) * 4;

    long long hbase = (long long)blockIdx.y * BM;
    const float* a0p = g_h + (hbase + arow     ) * INTER + af4;
    const float* a1p = g_h + (hbase + arow + 64) * INTER + af4;

    float4 c[2][8];
#pragma unroll
    for (int mi = 0; mi < 2; mi++)
#pragma unroll
        for (int ni = 0; ni < 8; ni++) c[mi][ni] = make_float4(0.f, 0.f, 0.f, 0.f);

    int w    = tid >> 5;
    int lane = tid & 31;
    int wrow = (w & 3) * 32;
    int wcol = (w >> 2) * 64;
    int g    = lane >> 2;
    int q    = lane & 3;

    auto load_tile = [&](int buf, int k0){
        cp_async16(&As[buf][arow     ][af4], a0p + k0);
        cp_async16(&As[buf][arow + 64][af4], a1p + k0);
        cp_async16(&Bs[buf][brow     ][bf4], wp + (size_t)(k0 + brow    ) * HID + n0 + bf4);
        cp_async16(&Bs[buf][brow + 8 ][bf4], wp + (size_t)(k0 + brow + 8) * HID + n0 + bf4);
    };

    load_tile(0, 0);
    cp_commit();

    const int KT = INTER / BK;   // 256
    for (int it = 0; it < KT; it++){
        int cur = it & 1;
        if (it + 1 < KT) load_tile(cur ^ 1, (it + 1) * BK);
        cp_commit();
        cp_wait1();
        __syncthreads();
#pragma unroll
        for (int kk = 0; kk < 2; kk++){
            int ko = kk * 8;
            uint32_t a[2][4];
#pragma unroll
            for (int mi = 0; mi < 2; mi++){
                int rb = wrow + mi * 16;
                a[mi][0] = to_tf32(As[cur][rb + g    ][ko + q    ]);
                a[mi][1] = to_tf32(As[cur][rb + g + 8][ko + q    ]);
                a[mi][2] = to_tf32(As[cur][rb + g    ][ko + q + 4]);
                a[mi][3] = to_tf32(As[cur][rb + g + 8][ko + q + 4]);
            }
#pragma unroll
            for (int ni = 0; ni < 8; ni++){
                int col = wcol + ni * 8 + g;
                uint32_t b0 = to_tf32(Bs[cur][ko + q    ][col]);
                uint32_t b1 = to_tf32(Bs[cur][ko + q + 4][col]);
#pragma unroll
                for (int mi = 0; mi < 2; mi++)
                    mma8(c[mi][ni], a[mi][0], a[mi][1], a[mi][2], a[mi][3], b0, b1);
            }
        }
        __syncthreads();
    }

    // epilogue: weighted scatter-add into output
#pragma unroll
    for (int mi = 0; mi < 2; mi++){
        int r0 = wrow + mi * 16 + g;
        float wt0 = s_w[r0];     int tok0 = s_tok[r0];
        float wt1 = s_w[r0 + 8]; int tok1 = s_tok[r0 + 8];
#pragma unroll
        for (int ni = 0; ni < 8; ni++){
            int col = n0 + wcol + ni * 8 + q * 2;
            float4 v = c[mi][ni];
            if (wt0 != 0.f){
                atomicAdd(&out[(size_t)tok0 * HID + col    ], wt0 * v.x);
                atomicAdd(&out[(size_t)tok0 * HID + col + 1], wt0 * v.y);
            }
            if (wt1 != 0.f){
                atomicAdd(&out[(size_t)tok1 * HID + col    ], wt1 * v.z);
                atomicAdd(&out[(size_t)tok1 * HID + col + 1], wt1 * v.w);
            }
        }
    }
}

// ---------------- entry point ----------------
extern "C" void kernel_launch(void* const* d_in, const int* in_sizes, int n_in,
                              void* d_out, int out_size){
    const float* x  = (const float*)d_in[0];
    const float* rw = (const float*)d_in[1];
    const float* w1 = (const float*)d_in[2];
    const float* w2 = (const float*)d_in[3];
    float* out = (float*)d_out;

    k_init<<<2048, 256>>>(out, out_size);
    k_router<<<NT / 8, 256>>>(x, rw);
    k_setup<<<1, 32>>>(out, out_size);
    dim3 grid1(INTER / BN, MAX_TILES);
    k_gemm1<<<grid1, 256>>>(x, w1);
    dim3 grid2(HID / BN, MAX_TILES);
    k_gemm2<<<grid2, 256>>>(w2, out);
}